// round 15
// baseline (speedup 1.0000x reference)
#include <cuda_runtime.h>
#include <math.h>

// Problem shape (fixed by the reference)
#define NB     16
#define NS     8192
#define NKV    512
#define NE     512
#define NH     8
#define ND     64
#define NCHUNK 8
#define CHUNK  1024
#define TILE   32
#define NTILES (CHUNK/TILE)   // 32
#define TB     512
#define ROWF   516            // padded kv row stride in floats (129 float4)

// Scratch (device globals; allocations forbidden)
__device__ __align__(16) float g_q[NB*NE];
__device__ __align__(16) float g_P[NB*NH*NKV];
__device__ __align__(16) float g_partC[(size_t)NB*NCHUNK*NH*NKV];
__device__ __align__(16) float g_partZ[NB*NCHUNK*NH];
__device__ __align__(16) float g_cbar[NB*NH*NKV];
__device__ __align__(16) float g_ctx[NB*NE];

__device__ __forceinline__ void cpa16(unsigned dst, const void* src){
    asm volatile("cp.async.cg.shared.global [%0], [%1], 16;" :: "r"(dst), "l"(src));
}
__device__ __forceinline__ unsigned to_tf32(float v){
    unsigned r; asm("cvt.rna.tf32.f32 %0, %1;" : "=r"(r) : "f"(v)); return r;
}
__device__ __forceinline__ void mma_tf32(
    float& c0, float& c1, float& c2, float& c3,
    unsigned a0, unsigned a1, unsigned a2, unsigned a3,
    unsigned b0, unsigned b1)
{
    asm volatile(
        "mma.sync.aligned.m16n8k8.row.col.f32.tf32.tf32.f32 "
        "{%0,%1,%2,%3}, {%4,%5,%6,%7}, {%8,%9}, {%0,%1,%2,%3};"
        : "+f"(c0), "+f"(c1), "+f"(c2), "+f"(c3)
        : "r"(a0), "r"(a1), "r"(a2), "r"(a3), "r"(b0), "r"(b1));
}

// ---------------------------------------------------------------------------
// A1: q[b,e] = query[b,:] @ Wq[:,e] + bq[e].
// ---------------------------------------------------------------------------
__global__ void __launch_bounds__(256) kernA1(
    const float* __restrict__ query, const float* __restrict__ Wq,
    const float* __restrict__ bq)
{
    __shared__ float qs[NKV];
    __shared__ float red[256];
    const int b = blockIdx.x, eb = blockIdx.y, t = threadIdx.x;
    for (int i = t; i < NKV; i += 256) qs[i] = query[b*NKV + i];
    __syncthreads();
    const int e = eb*64 + (t & 63), kp = t >> 6;
    const float* q  = qs + kp*128;
    const float* wq = Wq + (size_t)(kp*128)*NE + e;
    float s0=0,s1=0,s2=0,s3=0,s4=0,s5=0,s6=0,s7=0;
    #pragma unroll 4
    for (int j = 0; j < 128; j += 8) {
        s0 = fmaf(q[j+0], wq[(size_t)(j+0)*NE], s0);
        s1 = fmaf(q[j+1], wq[(size_t)(j+1)*NE], s1);
        s2 = fmaf(q[j+2], wq[(size_t)(j+2)*NE], s2);
        s3 = fmaf(q[j+3], wq[(size_t)(j+3)*NE], s3);
        s4 = fmaf(q[j+4], wq[(size_t)(j+4)*NE], s4);
        s5 = fmaf(q[j+5], wq[(size_t)(j+5)*NE], s5);
        s6 = fmaf(q[j+6], wq[(size_t)(j+6)*NE], s6);
        s7 = fmaf(q[j+7], wq[(size_t)(j+7)*NE], s7);
    }
    red[t] = ((s0+s1)+(s2+s3))+((s4+s5)+(s6+s7));
    __syncthreads();
    if (t < 64)
        g_q[b*NE + e] = ((red[t]+red[t+64])+(red[t+128]+red[t+192])) + bq[e];
}

// ---------------------------------------------------------------------------
// A2: P[b,h,j] = 0.125 * sum_d g_q[b,h*64+d] * Wk[j,h*64+d]
// ---------------------------------------------------------------------------
__global__ void __launch_bounds__(256) kernA2(const float* __restrict__ Wk)
{
    __shared__ float wks[64*65];
    __shared__ float qhs[16*64];
    const int jb = blockIdx.x, h = blockIdx.y, t = threadIdx.x;

    for (int i = t; i < 64*16; i += 256) {
        int j = i >> 4, d4 = i & 15;
        float4 v = *(const float4*)(Wk + (size_t)(jb*64 + j)*NE + h*ND + d4*4);
        wks[j*65 + d4*4+0] = v.x; wks[j*65 + d4*4+1] = v.y;
        wks[j*65 + d4*4+2] = v.z; wks[j*65 + d4*4+3] = v.w;
    }
    for (int i = t; i < 16*64; i += 256) {
        int bb = i >> 6, d = i & 63;
        qhs[bb*64 + d] = g_q[bb*NE + h*ND + d];
    }
    __syncthreads();

    const int j = t & 63, bg = t >> 6;
    float acc[4] = {0.f,0.f,0.f,0.f};
    const float* wr = wks + j*65;
    #pragma unroll
    for (int d = 0; d < 64; ++d) {
        float wv = wr[d];
        #pragma unroll
        for (int bb = 0; bb < 4; ++bb)
            acc[bb] = fmaf(wv, qhs[(bg*4 + bb)*64 + d], acc[bb]);
    }
    #pragma unroll
    for (int bb = 0; bb < 4; ++bb)
        g_P[((size_t)(bg*4 + bb)*NH + h)*NKV + jb*64 + j] = acc[bb]*0.125f;
}

// ---------------------------------------------------------------------------
// B: fused pass over kv, both inner products on tensor cores (tf32 mma).
// 512 threads / 16 warps (4 per SMSP). Per 32-row tile:
//  1) logit GEMM: warp (mb=w&1, ks=w>>1) -> partial C[16 rows][8 heads]
//     over its 64-wide K slice (8 mmas); partials -> smem.
//  2) 256 threads reduce 8 K slices, one exp; w tf32-rounded, SAME value
//     feeds Z and the stored weight.
//  3) accumulation GEMM: ctx^T += kv^T @ w; warp owns 32 cols (2 m16-tiles)
//     x 8 heads x K=32 (4 k8-chunks) = 8 mmas; acc (8 regs) persists across
//     tiles; each (col,head) owned by ONE warp -> direct STG epilogue.
// No-max softmax (|logit| < ~3). Triple-buffered cp.async ring; ROWF=516
// makes logit A-frags conflict-free (accum A-frags 2-way).
// ---------------------------------------------------------------------------
__global__ void __launch_bounds__(TB, 1) kernB(const float* __restrict__ kv)
{
    extern __shared__ float sh[];
    float* kvs  = sh;                          // [3][TILE][ROWF]
    float* wsm  = sh + 3*TILE*ROWF;            // [2][TILE][NH] tf32 weights
    float* part = wsm + 2*TILE*NH;             // [16 warps][16 rows][8 heads]
    float* zs   = part + 16*16*8;              // [256]

    const int tid  = threadIdx.x;
    const int wid  = tid >> 5, lane = tid & 31;
    const int chunk = blockIdx.x, b = blockIdx.y;

    // shared lane decomposition for mma fragments
    const int gr = lane >> 2, gc = lane & 3;
    // logit-phase mapping
    const int mb = wid & 1, ks = wid >> 1;     // 16-row block, 64-wide K slice
    // reduction mapping (tid < 256)
    const int rrow = tid >> 3, rh = tid & 7;
    const int rmb = rrow >> 4, rr16 = rrow & 15;
    // accum-phase mapping: warp owns cols wid*32..+31

    // Logit B fragments: P^T slice (64-wide), tf32, in registers.
    unsigned bq0[8], bq1[8];
    {
        const float* Ph = g_P + ((size_t)b*NH + gr)*NKV + ks*64 + gc;
        #pragma unroll
        for (int kb = 0; kb < 8; ++kb) {
            bq0[kb] = to_tf32(Ph[kb*8]);
            bq1[kb] = to_tf32(Ph[kb*8 + 4]);
        }
    }

    // Accum accumulators: D^T[wid*32+mt*16+{gr,gr+8}][{2gc,2gc+1}]
    float acc[2][4];
    #pragma unroll
    for (int mt = 0; mt < 2; ++mt)
        #pragma unroll
        for (int c = 0; c < 4; ++c) acc[mt][c] = 0.f;
    float zacc = 0.f;

    const unsigned kvs_u = (unsigned)__cvta_generic_to_shared(kvs);
    const float4* src_base = (const float4*)kv
        + ((size_t)b*NS + (size_t)chunk*CHUNK)*(NKV/4);

    // prologue: stage tiles 0 and 1 (padded rows: dst float4 index r*129+c4)
    #pragma unroll
    for (int pt = 0; pt < 2; ++pt) {
        const float4* s = src_base + (size_t)pt*TILE*(NKV/4);
        unsigned dst = kvs_u + (unsigned)(pt*TILE*ROWF*4);
        #pragma unroll
        for (int k = 0; k < (TILE*NKV/4)/TB; ++k) {
            int i = tid + k*TB;
            int r = i >> 7, c4 = i & 127;
            cpa16(dst + (unsigned)((r*129 + c4)*16), s + i);
        }
        asm volatile("cp.async.commit_group;");
    }

    for (int t = 0; t < NTILES; ++t) {
        if (t < NTILES-1) asm volatile("cp.async.wait_group 1;");
        else              asm volatile("cp.async.wait_group 0;");
        __syncthreads();                                   // B1

        if (t + 2 < NTILES) {   // stage t+2 into buffer (t+2)%3
            const float4* s = src_base + (size_t)(t+2)*TILE*(NKV/4);
            unsigned dst = kvs_u + (unsigned)(((t+2)%3)*TILE*ROWF*4);
            #pragma unroll
            for (int k = 0; k < (TILE*NKV/4)/TB; ++k) {
                int i = tid + k*TB;
                int r = i >> 7, c4 = i & 127;
                cpa16(dst + (unsigned)((r*129 + c4)*16), s + i);
            }
            asm volatile("cp.async.commit_group;");
        }

        const float* buf = kvs + (t%3)*TILE*ROWF;

        // ---- 1) logit mma: partial C for (mb, ks) over 64-wide K slice ----
        {
            const float* pa = buf + (mb*16 + gr)*ROWF + ks*64 + gc;
            float c0=0.f, c1=0.f, c2=0.f, c3=0.f;
            #pragma unroll
            for (int kb = 0; kb < 8; ++kb) {
                const float* p = pa + kb*8;
                unsigned a0 = __float_as_uint(p[0]);
                unsigned a1 = __float_as_uint(p[8*ROWF]);
                unsigned a2 = __float_as_uint(p[4]);
                unsigned a3 = __float_as_uint(p[8*ROWF + 4]);
                mma_tf32(c0, c1, c2, c3, a0, a1, a2, a3, bq0[kb], bq1[kb]);
            }
            *(float2*)(part + wid*128 + gr*8 + 2*gc)     = make_float2(c0, c1);
            *(float2*)(part + wid*128 + (gr+8)*8 + 2*gc) = make_float2(c2, c3);
        }
        __syncthreads();                                   // B2

        // ---- 2) reduce 8 K slices, exp, tf32-round, store ----
        if (tid < 256) {
            const int off = rr16*8 + rh;
            float p0 = part[(0*2+rmb)*128 + off], p1 = part[(1*2+rmb)*128 + off];
            float p2 = part[(2*2+rmb)*128 + off], p3 = part[(3*2+rmb)*128 + off];
            float p4 = part[(4*2+rmb)*128 + off], p5 = part[(5*2+rmb)*128 + off];
            float p6 = part[(6*2+rmb)*128 + off], p7 = part[(7*2+rmb)*128 + off];
            float lg = ((p0+p1)+(p2+p3)) + ((p4+p5)+(p6+p7));
            float w = __expf(lg);
            float wf = __uint_as_float(to_tf32(w));   // tf32-rounded weight
            zacc += wf;                               // Z from the SAME value
            wsm[(t & 1)*TILE*NH + rrow*NH + rh] = wf;
        }
        __syncthreads();                                   // B3

        // ---- 3) accumulation mma: ctx^T += kv^T @ w ----
        {
            const float* wt = wsm + (t & 1)*TILE*NH;
            const int col0 = wid*32;
            #pragma unroll
            for (int kc = 0; kc < 4; ++kc) {
                unsigned b0 = __float_as_uint(wt[(kc*8 + gc)*NH + gr]);
                unsigned b1 = __float_as_uint(wt[(kc*8 + gc + 4)*NH + gr]);
                const float* ar0 = buf + (kc*8 + gc)*ROWF + col0 + gr;
                const float* ar1 = buf + (kc*8 + gc + 4)*ROWF + col0 + gr;
                #pragma unroll
                for (int mt = 0; mt < 2; ++mt) {
                    unsigned a0 = __float_as_uint(ar0[mt*16]);
                    unsigned a1 = __float_as_uint(ar0[mt*16 + 8]);
                    unsigned a2 = __float_as_uint(ar1[mt*16]);
                    unsigned a3 = __float_as_uint(ar1[mt*16 + 8]);
                    mma_tf32(acc[mt][0], acc[mt][1], acc[mt][2], acc[mt][3],
                             a0, a1, a2, a3, b0, b1);
                }
            }
        }
    }

    // ---- epilogue: direct STG (each warp owns its cols x all heads) ----
    if (tid < 256) zs[tid] = zacc;
    __syncthreads();

    const int part_i = b*NCHUNK + chunk;
    {
        float* pc = g_partC + (size_t)part_i*NH*NKV;
        const int col0 = wid*32 + gr;
        #pragma unroll
        for (int mt = 0; mt < 2; ++mt) {
            const int col = col0 + mt*16;
            pc[(size_t)(2*gc  )*NKV + col    ] = acc[mt][0];
            pc[(size_t)(2*gc+1)*NKV + col    ] = acc[mt][1];
            pc[(size_t)(2*gc  )*NKV + col + 8] = acc[mt][2];
            pc[(size_t)(2*gc+1)*NKV + col + 8] = acc[mt][3];
        }
    }
    if (tid < NH) {
        // zacc per thread covers head = tid&7 over its rows
        float Z = 0.f;
        #pragma unroll
        for (int j = 0; j < 32; ++j) Z += zs[j*8 + tid];
        g_partZ[part_i*NH + tid] = Z;
    }
}

// ---------------------------------------------------------------------------
// C1: cbar[b,h,j] = (sum_i partC[b,i,h,j]) / Z[b,h].  grid 64 x 256
// ---------------------------------------------------------------------------
__global__ void __launch_bounds__(256) kernC1()
{
    const int idx = blockIdx.x*256 + threadIdx.x;      // 16384 float4 slots
    const int b = idx >> 10, rem = idx & 1023, h = rem >> 7, j4 = rem & 127;
    float Z = 0.f;
    #pragma unroll
    for (int i = 0; i < NCHUNK; ++i) Z += g_partZ[(b*NCHUNK + i)*NH + h];
    const float invZ = 1.0f / Z;
    float4 s = make_float4(0.f,0.f,0.f,0.f);
    #pragma unroll
    for (int i = 0; i < NCHUNK; ++i) {
        const float4* p = (const float4*)(g_partC + (((size_t)(b*NCHUNK + i)*NH + h) << 9));
        float4 v = p[j4];
        s.x += v.x; s.y += v.y; s.z += v.z; s.w += v.w;
    }
    s.x *= invZ; s.y *= invZ; s.z *= invZ; s.w *= invZ;
    ((float4*)g_cbar)[((size_t)(b*NH + h) << 7) + j4] = s;
}

// ---------------------------------------------------------------------------
// C2: ctx[b, h*64+col] = cbar[b,h,:] @ Wv[:, h*64+col] + bv.
// ---------------------------------------------------------------------------
__global__ void __launch_bounds__(256) kernC2(
    const float* __restrict__ Wv, const float* __restrict__ bv)
{
    __shared__ float cb_s[NKV];
    __shared__ float red[256];
    const int b = blockIdx.x, h = blockIdx.y, t = threadIdx.x;
    for (int i = t; i < NKV; i += 256) cb_s[i] = g_cbar[(size_t)(b*NH + h)*NKV + i];
    __syncthreads();
    const int col = h*64 + (t & 63), kp = t >> 6;
    const float* c  = cb_s + kp*128;
    const float* wv = Wv + (size_t)(kp*128)*NE + col;
    float s0=0,s1=0,s2=0,s3=0,s4=0,s5=0,s6=0,s7=0;
    #pragma unroll 4
    for (int j = 0; j < 128; j += 8) {
        s0 = fmaf(c[j+0], wv[(size_t)(j+0)*NE], s0);
        s1 = fmaf(c[j+1], wv[(size_t)(j+1)*NE], s1);
        s2 = fmaf(c[j+2], wv[(size_t)(j+2)*NE], s2);
        s3 = fmaf(c[j+3], wv[(size_t)(j+3)*NE], s3);
        s4 = fmaf(c[j+4], wv[(size_t)(j+4)*NE], s4);
        s5 = fmaf(c[j+5], wv[(size_t)(j+5)*NE], s5);
        s6 = fmaf(c[j+6], wv[(size_t)(j+6)*NE], s6);
        s7 = fmaf(c[j+7], wv[(size_t)(j+7)*NE], s7);
    }
    red[t] = ((s0+s1)+(s2+s3))+((s4+s5)+(s6+s7));
    __syncthreads();
    if (t < 64)
        g_ctx[b*NE + col] = ((red[t]+red[t+64])+(red[t+128]+red[t+192])) + bv[col];
}

// ---------------------------------------------------------------------------
// D: out[b] = ctx[b] @ Wo + bo.
// ---------------------------------------------------------------------------
__global__ void __launch_bounds__(256) kernD(
    const float* __restrict__ Wo, const float* __restrict__ bo,
    float* __restrict__ out)
{
    __shared__ float cs[NE];
    __shared__ float red[256];
    const int b = blockIdx.x, cb = blockIdx.y, t = threadIdx.x;
    for (int i = t; i < NE; i += 256) cs[i] = g_ctx[b*NE + i];
    __syncthreads();
    const int col = cb*64 + (t & 63), kp = t >> 6;
    const float* c  = cs + kp*128;
    const float* wo = Wo + (size_t)(kp*128)*NE + col;
    float s0=0,s1=0,s2=0,s3=0,s4=0,s5=0,s6=0,s7=0;
    #pragma unroll 4
    for (int j = 0; j < 128; j += 8) {
        s0 = fmaf(c[j+0], wo[(size_t)(j+0)*NE], s0);
        s1 = fmaf(c[j+1], wo[(size_t)(j+1)*NE], s1);
        s2 = fmaf(c[j+2], wo[(size_t)(j+2)*NE], s2);
        s3 = fmaf(c[j+3], wo[(size_t)(j+3)*NE], s3);
        s4 = fmaf(c[j+4], wo[(size_t)(j+4)*NE], s4);
        s5 = fmaf(c[j+5], wo[(size_t)(j+5)*NE], s5);
        s6 = fmaf(c[j+6], wo[(size_t)(j+6)*NE], s6);
        s7 = fmaf(c[j+7], wo[(size_t)(j+7)*NE], s7);
    }
    red[t] = ((s0+s1)+(s2+s3))+((s4+s5)+(s6+s7));
    __syncthreads();
    if (t < 64)
        out[b*NE + col] = ((red[t]+red[t+64])+(red[t+128]+red[t+192])) + bo[col];
}

// ---------------------------------------------------------------------------
extern "C" void kernel_launch(void* const* d_in, const int* in_sizes, int n_in,
                              void* d_out, int out_size)
{
    (void)in_sizes; (void)n_in; (void)out_size;
    const float* query = (const float*)d_in[0];
    const float* kv    = (const float*)d_in[1];
    const float* Wq    = (const float*)d_in[2];
    const float* bq    = (const float*)d_in[3];
    const float* Wk    = (const float*)d_in[4];
    // d_in[5] = bk: softmax-invariant, unused
    const float* Wv    = (const float*)d_in[6];
    const float* bv    = (const float*)d_in[7];
    const float* Wo    = (const float*)d_in[8];
    const float* bo    = (const float*)d_in[9];
    float* out = (float*)d_out;

    const size_t shmB = (size_t)(3*TILE*ROWF + 2*TILE*NH + 16*16*8 + 256)
                        * sizeof(float);
    cudaFuncSetAttribute(kernB, cudaFuncAttributeMaxDynamicSharedMemorySize, (int)shmB);

    kernA1<<<dim3(NB, 8), 256>>>(query, Wq, bq);
    kernA2<<<dim3(8, NH), 256>>>(Wk);
    kernB <<<dim3(NCHUNK, NB), TB, shmB>>>(kv);
    kernC1<<<64, 256>>>();
    kernC2<<<dim3(NB, NH), 256>>>(Wv, bv);
    kernD <<<dim3(NB, 8), 256>>>(Wo, bo, out);
}

// round 16
// speedup vs baseline: 1.0182x; 1.0182x over previous
#include <cuda_runtime.h>
#include <math.h>

// Problem shape (fixed by the reference)
#define NB     16
#define NS     8192
#define NKV    512
#define NE     512
#define NH     8
#define ND     64
#define NCHUNK 8
#define CHUNK  1024
#define TILE   32
#define NTILES (CHUNK/TILE)   // 32
#define TB     256
#define ROWF   516            // padded kv row stride in floats (129 float4)

// Scratch (device globals; allocations forbidden)
__device__ __align__(16) float g_q[NB*NE];
__device__ __align__(16) float g_P[NB*NH*NKV];
__device__ __align__(16) float g_partC[(size_t)NB*NCHUNK*NH*NKV];
__device__ __align__(16) float g_partZ[NB*NCHUNK*NH];
__device__ __align__(16) float g_cbar[NB*NH*NKV];
__device__ __align__(16) float g_ctx[NB*NE];

__device__ __forceinline__ void cpa16(unsigned dst, const void* src){
    asm volatile("cp.async.cg.shared.global [%0], [%1], 16;" :: "r"(dst), "l"(src));
}
__device__ __forceinline__ unsigned to_tf32(float v){
    unsigned r; asm("cvt.rna.tf32.f32 %0, %1;" : "=r"(r) : "f"(v)); return r;
}
__device__ __forceinline__ void mma_tf32(
    float& c0, float& c1, float& c2, float& c3,
    unsigned a0, unsigned a1, unsigned a2, unsigned a3,
    unsigned b0, unsigned b1)
{
    asm volatile(
        "mma.sync.aligned.m16n8k8.row.col.f32.tf32.tf32.f32 "
        "{%0,%1,%2,%3}, {%4,%5,%6,%7}, {%8,%9}, {%0,%1,%2,%3};"
        : "+f"(c0), "+f"(c1), "+f"(c2), "+f"(c3)
        : "r"(a0), "r"(a1), "r"(a2), "r"(a3), "r"(b0), "r"(b1));
}

// ---------------------------------------------------------------------------
// A1: q[b,e] = query[b,:] @ Wq[:,e] + bq[e].
// ---------------------------------------------------------------------------
__global__ void __launch_bounds__(256) kernA1(
    const float* __restrict__ query, const float* __restrict__ Wq,
    const float* __restrict__ bq)
{
    __shared__ float qs[NKV];
    __shared__ float red[256];
    const int b = blockIdx.x, eb = blockIdx.y, t = threadIdx.x;
    for (int i = t; i < NKV; i += 256) qs[i] = query[b*NKV + i];
    __syncthreads();
    const int e = eb*64 + (t & 63), kp = t >> 6;
    const float* q  = qs + kp*128;
    const float* wq = Wq + (size_t)(kp*128)*NE + e;
    float s0=0,s1=0,s2=0,s3=0,s4=0,s5=0,s6=0,s7=0;
    #pragma unroll 4
    for (int j = 0; j < 128; j += 8) {
        s0 = fmaf(q[j+0], wq[(size_t)(j+0)*NE], s0);
        s1 = fmaf(q[j+1], wq[(size_t)(j+1)*NE], s1);
        s2 = fmaf(q[j+2], wq[(size_t)(j+2)*NE], s2);
        s3 = fmaf(q[j+3], wq[(size_t)(j+3)*NE], s3);
        s4 = fmaf(q[j+4], wq[(size_t)(j+4)*NE], s4);
        s5 = fmaf(q[j+5], wq[(size_t)(j+5)*NE], s5);
        s6 = fmaf(q[j+6], wq[(size_t)(j+6)*NE], s6);
        s7 = fmaf(q[j+7], wq[(size_t)(j+7)*NE], s7);
    }
    red[t] = ((s0+s1)+(s2+s3))+((s4+s5)+(s6+s7));
    __syncthreads();
    if (t < 64)
        g_q[b*NE + e] = ((red[t]+red[t+64])+(red[t+128]+red[t+192])) + bq[e];
}

// ---------------------------------------------------------------------------
// A2: P[b,h,j] = 0.125 * sum_d g_q[b,h*64+d] * Wk[j,h*64+d]
// ---------------------------------------------------------------------------
__global__ void __launch_bounds__(256) kernA2(const float* __restrict__ Wk)
{
    __shared__ float wks[64*65];
    __shared__ float qhs[16*64];
    const int jb = blockIdx.x, h = blockIdx.y, t = threadIdx.x;

    for (int i = t; i < 64*16; i += 256) {
        int j = i >> 4, d4 = i & 15;
        float4 v = *(const float4*)(Wk + (size_t)(jb*64 + j)*NE + h*ND + d4*4);
        wks[j*65 + d4*4+0] = v.x; wks[j*65 + d4*4+1] = v.y;
        wks[j*65 + d4*4+2] = v.z; wks[j*65 + d4*4+3] = v.w;
    }
    for (int i = t; i < 16*64; i += 256) {
        int bb = i >> 6, d = i & 63;
        qhs[bb*64 + d] = g_q[bb*NE + h*ND + d];
    }
    __syncthreads();

    const int j = t & 63, bg = t >> 6;
    float acc[4] = {0.f,0.f,0.f,0.f};
    const float* wr = wks + j*65;
    #pragma unroll
    for (int d = 0; d < 64; ++d) {
        float wv = wr[d];
        #pragma unroll
        for (int bb = 0; bb < 4; ++bb)
            acc[bb] = fmaf(wv, qhs[(bg*4 + bb)*64 + d], acc[bb]);
    }
    #pragma unroll
    for (int bb = 0; bb < 4; ++bb)
        g_P[((size_t)(bg*4 + bb)*NH + h)*NKV + jb*64 + j] = acc[bb]*0.125f;
}

// ---------------------------------------------------------------------------
// B: fused pass over kv, both inner products on tensor cores (tf32 mma),
// SOFTWARE-PIPELINED phases: iteration t runs logit(t) and accum(t-1)
// back-to-back (different kv buffers, different wsm parity), then ONE
// barrier, then the reduce/exp for t. 2 barriers/tile instead of 3.
// 256 threads / 8 warps. Prefetch distance 1; buffers t-1, t, t+1 live
// (distinct mod 3; cp.async target (t+1)%3 last held t-2 whose accum
// finished before the previous barrier).
//  logit:  warp (mb=w&1, ks=w>>1) -> partial C[16 rows][8 heads] over a
//          128-wide K slice (16 mmas); partials -> smem.
//  reduce: 256 threads sum 4 K slices, one exp; w tf32-rounded, SAME value
//          feeds Z and the stored weight.
//  accum:  ctx^T += kv^T @ w; warp owns 64 cols x 8 heads x K=32 =
//          16 mmas; acc (16 regs) persists; direct STG epilogue.
// No-max softmax (|logit| < ~3). ROWF=516: logit A-frags conflict-free.
// ---------------------------------------------------------------------------
__global__ void __launch_bounds__(TB, 1) kernB(const float* __restrict__ kv)
{
    extern __shared__ float sh[];
    float* kvs  = sh;                          // [3][TILE][ROWF]
    float* wsm  = sh + 3*TILE*ROWF;            // [2][TILE][NH] tf32 weights
    float* part = wsm + 2*TILE*NH;             // [8 warps][16 rows][8 heads]
    float* zs   = part + 8*16*8;               // [256]

    const int tid  = threadIdx.x;
    const int wid  = tid >> 5, lane = tid & 31;
    const int chunk = blockIdx.x, b = blockIdx.y;

    // shared lane decomposition for mma fragments
    const int gr = lane >> 2, gc = lane & 3;
    // logit-phase mapping
    const int mb = wid & 1, ks = wid >> 1;
    // reduction mapping
    const int rrow = tid >> 3, rh = tid & 7;
    const int rmb = rrow >> 4, rr16 = rrow & 15;
    // accum-phase mapping: warp owns cols wid*64..+63

    // Logit B fragments: P^T slice, tf32, in registers.
    unsigned bq0[16], bq1[16];
    {
        const float* Ph = g_P + ((size_t)b*NH + gr)*NKV + ks*128 + gc;
        #pragma unroll
        for (int kb = 0; kb < 16; ++kb) {
            bq0[kb] = to_tf32(Ph[kb*8]);
            bq1[kb] = to_tf32(Ph[kb*8 + 4]);
        }
    }

    // Accum accumulators: D^T[col0+mt*16+{gr,gr+8}][{2gc,2gc+1}]
    float acc[4][4];
    #pragma unroll
    for (int mt = 0; mt < 4; ++mt)
        #pragma unroll
        for (int c = 0; c < 4; ++c) acc[mt][c] = 0.f;
    float zacc = 0.f;

    const unsigned kvs_u = (unsigned)__cvta_generic_to_shared(kvs);
    const float4* src_base = (const float4*)kv
        + ((size_t)b*NS + (size_t)chunk*CHUNK)*(NKV/4);

    // prologue: stage tile 0 (padded rows: dst float4 index r*129+c4)
    {
        const float4* s = src_base;
        #pragma unroll
        for (int k = 0; k < (TILE*NKV/4)/TB; ++k) {
            int i = tid + k*TB;
            int r = i >> 7, c4 = i & 127;
            cpa16(kvs_u + (unsigned)((r*129 + c4)*16), s + i);
        }
        asm volatile("cp.async.commit_group;");
    }

    // pipelined loop: iteration t does logit(t) + accum(t-1), then reduce(t).
    // t == NTILES runs only the trailing accum(NTILES-1).
    for (int t = 0; t <= NTILES; ++t) {
        if (t < NTILES) asm volatile("cp.async.wait_group 0;");
        __syncthreads();                                   // B1

        if (t + 1 < NTILES) {   // stage t+1 into buffer (t+1)%3
            const float4* s = src_base + (size_t)(t+1)*TILE*(NKV/4);
            unsigned dst = kvs_u + (unsigned)(((t+1)%3)*TILE*ROWF*4);
            #pragma unroll
            for (int k = 0; k < (TILE*NKV/4)/TB; ++k) {
                int i = tid + k*TB;
                int r = i >> 7, c4 = i & 127;
                cpa16(dst + (unsigned)((r*129 + c4)*16), s + i);
            }
            asm volatile("cp.async.commit_group;");
        }

        // ---- logit mma for tile t ----
        if (t < NTILES) {
            const float* buf = kvs + (t%3)*TILE*ROWF;
            const float* pa = buf + (mb*16 + gr)*ROWF + ks*128 + gc;
            float c0=0.f, c1=0.f, c2=0.f, c3=0.f;
            #pragma unroll
            for (int kb = 0; kb < 16; ++kb) {
                const float* p = pa + kb*8;
                unsigned a0 = __float_as_uint(p[0]);
                unsigned a1 = __float_as_uint(p[8*ROWF]);
                unsigned a2 = __float_as_uint(p[4]);
                unsigned a3 = __float_as_uint(p[8*ROWF + 4]);
                mma_tf32(c0, c1, c2, c3, a0, a1, a2, a3, bq0[kb], bq1[kb]);
            }
            *(float2*)(part + wid*128 + gr*8 + 2*gc)     = make_float2(c0, c1);
            *(float2*)(part + wid*128 + (gr+8)*8 + 2*gc) = make_float2(c2, c3);
        }

        // ---- accum mma for tile t-1 (overlaps logit, no barrier between) ----
        if (t >= 1) {
            const int tp = t - 1;
            const float* bufp = kvs + (tp%3)*TILE*ROWF;
            const float* wt = wsm + (tp & 1)*TILE*NH;
            const int col0 = wid*64;
            #pragma unroll
            for (int kc = 0; kc < 4; ++kc) {
                unsigned b0 = __float_as_uint(wt[(kc*8 + gc)*NH + gr]);
                unsigned b1 = __float_as_uint(wt[(kc*8 + gc + 4)*NH + gr]);
                const float* ar0 = bufp + (kc*8 + gc)*ROWF + col0 + gr;
                const float* ar1 = bufp + (kc*8 + gc + 4)*ROWF + col0 + gr;
                #pragma unroll
                for (int mt = 0; mt < 4; ++mt) {
                    unsigned a0 = __float_as_uint(ar0[mt*16]);
                    unsigned a1 = __float_as_uint(ar0[mt*16 + 8]);
                    unsigned a2 = __float_as_uint(ar1[mt*16]);
                    unsigned a3 = __float_as_uint(ar1[mt*16 + 8]);
                    mma_tf32(acc[mt][0], acc[mt][1], acc[mt][2], acc[mt][3],
                             a0, a1, a2, a3, b0, b1);
                }
            }
        }
        __syncthreads();                                   // B2: part ready

        // ---- reduce K slices for tile t, exp, tf32-round, publish wsm[t&1] ----
        if (t < NTILES) {
            const int off = rr16*8 + rh;
            float lg = (part[(rmb+0)*128 + off] + part[(rmb+2)*128 + off])
                     + (part[(rmb+4)*128 + off] + part[(rmb+6)*128 + off]);
            float w = __expf(lg);
            float wf = __uint_as_float(to_tf32(w));   // tf32-rounded weight
            zacc += wf;                               // Z from the SAME value
            wsm[(t & 1)*TILE*NH + rrow*NH + rh] = wf;
        }
    }

    // ---- epilogue: direct STG (each warp owns its cols x all heads) ----
    zs[tid] = zacc;
    __syncthreads();

    const int part_i = b*NCHUNK + chunk;
    {
        float* pc = g_partC + (size_t)part_i*NH*NKV;
        const int col0 = wid*64 + gr;
        #pragma unroll
        for (int mt = 0; mt < 4; ++mt) {
            const int col = col0 + mt*16;
            pc[(size_t)(2*gc  )*NKV + col    ] = acc[mt][0];
            pc[(size_t)(2*gc+1)*NKV + col    ] = acc[mt][1];
            pc[(size_t)(2*gc  )*NKV + col + 8] = acc[mt][2];
            pc[(size_t)(2*gc+1)*NKV + col + 8] = acc[mt][3];
        }
    }
    if (tid < NH) {
        float Z = 0.f;
        #pragma unroll
        for (int j = 0; j < 32; ++j) Z += zs[j*8 + tid];
        g_partZ[part_i*NH + tid] = Z;
    }
}

// ---------------------------------------------------------------------------
// C1: cbar[b,h,j] = (sum_i partC[b,i,h,j]) / Z[b,h].  grid 64 x 256
// ---------------------------------------------------------------------------
__global__ void __launch_bounds__(256) kernC1()
{
    const int idx = blockIdx.x*256 + threadIdx.x;      // 16384 float4 slots
    const int b = idx >> 10, rem = idx & 1023, h = rem >> 7, j4 = rem & 127;
    float Z = 0.f;
    #pragma unroll
    for (int i = 0; i < NCHUNK; ++i) Z += g_partZ[(b*NCHUNK + i)*NH + h];
    const float invZ = 1.0f / Z;
    float4 s = make_float4(0.f,0.f,0.f,0.f);
    #pragma unroll
    for (int i = 0; i < NCHUNK; ++i) {
        const float4* p = (const float4*)(g_partC + (((size_t)(b*NCHUNK + i)*NH + h) << 9));
        float4 v = p[j4];
        s.x += v.x; s.y += v.y; s.z += v.z; s.w += v.w;
    }
    s.x *= invZ; s.y *= invZ; s.z *= invZ; s.w *= invZ;
    ((float4*)g_cbar)[((size_t)(b*NH + h) << 7) + j4] = s;
}

// ---------------------------------------------------------------------------
// C2: ctx[b, h*64+col] = cbar[b,h,:] @ Wv[:, h*64+col] + bv.
// ---------------------------------------------------------------------------
__global__ void __launch_bounds__(256) kernC2(
    const float* __restrict__ Wv, const float* __restrict__ bv)
{
    __shared__ float cb_s[NKV];
    __shared__ float red[256];
    const int b = blockIdx.x, h = blockIdx.y, t = threadIdx.x;
    for (int i = t; i < NKV; i += 256) cb_s[i] = g_cbar[(size_t)(b*NH + h)*NKV + i];
    __syncthreads();
    const int col = h*64 + (t & 63), kp = t >> 6;
    const float* c  = cb_s + kp*128;
    const float* wv = Wv + (size_t)(kp*128)*NE + col;
    float s0=0,s1=0,s2=0,s3=0,s4=0,s5=0,s6=0,s7=0;
    #pragma unroll 4
    for (int j = 0; j < 128; j += 8) {
        s0 = fmaf(c[j+0], wv[(size_t)(j+0)*NE], s0);
        s1 = fmaf(c[j+1], wv[(size_t)(j+1)*NE], s1);
        s2 = fmaf(c[j+2], wv[(size_t)(j+2)*NE], s2);
        s3 = fmaf(c[j+3], wv[(size_t)(j+3)*NE], s3);
        s4 = fmaf(c[j+4], wv[(size_t)(j+4)*NE], s4);
        s5 = fmaf(c[j+5], wv[(size_t)(j+5)*NE], s5);
        s6 = fmaf(c[j+6], wv[(size_t)(j+6)*NE], s6);
        s7 = fmaf(c[j+7], wv[(size_t)(j+7)*NE], s7);
    }
    red[t] = ((s0+s1)+(s2+s3))+((s4+s5)+(s6+s7));
    __syncthreads();
    if (t < 64)
        g_ctx[b*NE + col] = ((red[t]+red[t+64])+(red[t+128]+red[t+192])) + bv[col];
}

// ---------------------------------------------------------------------------
// D: out[b] = ctx[b] @ Wo + bo.
// ---------------------------------------------------------------------------
__global__ void __launch_bounds__(256) kernD(
    const float* __restrict__ Wo, const float* __restrict__ bo,
    float* __restrict__ out)
{
    __shared__ float cs[NE];
    __shared__ float red[256];
    const int b = blockIdx.x, cb = blockIdx.y, t = threadIdx.x;
    for (int i = t; i < NE; i += 256) cs[i] = g_ctx[b*NE + i];
    __syncthreads();
    const int col = cb*64 + (t & 63), kp = t >> 6;
    const float* c  = cs + kp*128;
    const float* wo = Wo + (size_t)(kp*128)*NE + col;
    float s0=0,s1=0,s2=0,s3=0,s4=0,s5=0,s6=0,s7=0;
    #pragma unroll 4
    for (int j = 0; j < 128; j += 8) {
        s0 = fmaf(c[j+0], wo[(size_t)(j+0)*NE], s0);
        s1 = fmaf(c[j+1], wo[(size_t)(j+1)*NE], s1);
        s2 = fmaf(c[j+2], wo[(size_t)(j+2)*NE], s2);
        s3 = fmaf(c[j+3], wo[(size_t)(j+3)*NE], s3);
        s4 = fmaf(c[j+4], wo[(size_t)(j+4)*NE], s4);
        s5 = fmaf(c[j+5], wo[(size_t)(j+5)*NE], s5);
        s6 = fmaf(c[j+6], wo[(size_t)(j+6)*NE], s6);
        s7 = fmaf(c[j+7], wo[(size_t)(j+7)*NE], s7);
    }
    red[t] = ((s0+s1)+(s2+s3))+((s4+s5)+(s6+s7));
    __syncthreads();
    if (t < 64)
        out[b*NE + col] = ((red[t]+red[t+64])+(red[t+128]+red[t+192])) + bo[col];
}

// ---------------------------------------------------------------------------
extern "C" void kernel_launch(void* const* d_in, const int* in_sizes, int n_in,
                              void* d_out, int out_size)
{
    (void)in_sizes; (void)n_in; (void)out_size;
    const float* query = (const float*)d_in[0];
    const float* kv    = (const float*)d_in[1];
    const float* Wq    = (const float*)d_in[2];
    const float* bq    = (const float*)d_in[3];
    const float* Wk    = (const float*)d_in[4];
    // d_in[5] = bk: softmax-invariant, unused
    const float* Wv    = (const float*)d_in[6];
    const float* bv    = (const float*)d_in[7];
    const float* Wo    = (const float*)d_in[8];
    const float* bo    = (const float*)d_in[9];
    float* out = (float*)d_out;

    const size_t shmB = (size_t)(3*TILE*ROWF + 2*TILE*NH + 8*16*8 + 256)
                        * sizeof(float);
    cudaFuncSetAttribute(kernB, cudaFuncAttributeMaxDynamicSharedMemorySize, (int)shmB);

    kernA1<<<dim3(NB, 8), 256>>>(query, Wq, bq);
    kernA2<<<dim3(8, NH), 256>>>(Wk);
    kernB <<<dim3(NCHUNK, NB), TB, shmB>>>(kv);
    kernC1<<<64, 256>>>();
    kernC2<<<dim3(NB, NH), 256>>>(Wv, bv);
    kernD <<<dim3(NB, 8), 256>>>(Wo, bo, out);
}

// round 17
// speedup vs baseline: 1.0234x; 1.0051x over previous
#include <cuda_runtime.h>
#include <math.h>

// Problem shape (fixed by the reference)
#define NB     16
#define NS     8192
#define NKV    512
#define NE     512
#define NH     8
#define ND     64
#define NCHUNK 16
#define CHUNK  512
#define TILE   16
#define NTILES (CHUNK/TILE)   // 32
#define TB     256
#define ROWF   516            // padded kv row stride in floats (129 float4)

// Scratch (device globals; allocations forbidden)
__device__ __align__(16) float g_q[NB*NE];
__device__ __align__(16) float g_P[NB*NH*NKV];
__device__ __align__(16) float g_partC[(size_t)NB*NCHUNK*NH*NKV];
__device__ __align__(16) float g_partZ[NB*NCHUNK*NH];
__device__ __align__(16) float g_cbar[NB*NH*NKV];
__device__ __align__(16) float g_ctx[NB*NE];

__device__ __forceinline__ void cpa16(unsigned dst, const void* src){
    asm volatile("cp.async.cg.shared.global [%0], [%1], 16;" :: "r"(dst), "l"(src));
}
__device__ __forceinline__ unsigned to_tf32(float v){
    unsigned r; asm("cvt.rna.tf32.f32 %0, %1;" : "=r"(r) : "f"(v)); return r;
}
__device__ __forceinline__ void mma_tf32(
    float& c0, float& c1, float& c2, float& c3,
    unsigned a0, unsigned a1, unsigned a2, unsigned a3,
    unsigned b0, unsigned b1)
{
    asm volatile(
        "mma.sync.aligned.m16n8k8.row.col.f32.tf32.tf32.f32 "
        "{%0,%1,%2,%3}, {%4,%5,%6,%7}, {%8,%9}, {%0,%1,%2,%3};"
        : "+f"(c0), "+f"(c1), "+f"(c2), "+f"(c3)
        : "r"(a0), "r"(a1), "r"(a2), "r"(a3), "r"(b0), "r"(b1));
}

// ---------------------------------------------------------------------------
// A1: q[b,e] = query[b,:] @ Wq[:,e] + bq[e].
// ---------------------------------------------------------------------------
__global__ void __launch_bounds__(256) kernA1(
    const float* __restrict__ query, const float* __restrict__ Wq,
    const float* __restrict__ bq)
{
    __shared__ float qs[NKV];
    __shared__ float red[256];
    const int b = blockIdx.x, eb = blockIdx.y, t = threadIdx.x;
    for (int i = t; i < NKV; i += 256) qs[i] = query[b*NKV + i];
    __syncthreads();
    const int e = eb*64 + (t & 63), kp = t >> 6;
    const float* q  = qs + kp*128;
    const float* wq = Wq + (size_t)(kp*128)*NE + e;
    float s0=0,s1=0,s2=0,s3=0,s4=0,s5=0,s6=0,s7=0;
    #pragma unroll 4
    for (int j = 0; j < 128; j += 8) {
        s0 = fmaf(q[j+0], wq[(size_t)(j+0)*NE], s0);
        s1 = fmaf(q[j+1], wq[(size_t)(j+1)*NE], s1);
        s2 = fmaf(q[j+2], wq[(size_t)(j+2)*NE], s2);
        s3 = fmaf(q[j+3], wq[(size_t)(j+3)*NE], s3);
        s4 = fmaf(q[j+4], wq[(size_t)(j+4)*NE], s4);
        s5 = fmaf(q[j+5], wq[(size_t)(j+5)*NE], s5);
        s6 = fmaf(q[j+6], wq[(size_t)(j+6)*NE], s6);
        s7 = fmaf(q[j+7], wq[(size_t)(j+7)*NE], s7);
    }
    red[t] = ((s0+s1)+(s2+s3))+((s4+s5)+(s6+s7));
    __syncthreads();
    if (t < 64)
        g_q[b*NE + e] = ((red[t]+red[t+64])+(red[t+128]+red[t+192])) + bq[e];
}

// ---------------------------------------------------------------------------
// A2: P[b,h,j] = 0.125 * sum_d g_q[b,h*64+d] * Wk[j,h*64+d]
// ---------------------------------------------------------------------------
__global__ void __launch_bounds__(256) kernA2(const float* __restrict__ Wk)
{
    __shared__ float wks[64*65];
    __shared__ float qhs[16*64];
    const int jb = blockIdx.x, h = blockIdx.y, t = threadIdx.x;

    for (int i = t; i < 64*16; i += 256) {
        int j = i >> 4, d4 = i & 15;
        float4 v = *(const float4*)(Wk + (size_t)(jb*64 + j)*NE + h*ND + d4*4);
        wks[j*65 + d4*4+0] = v.x; wks[j*65 + d4*4+1] = v.y;
        wks[j*65 + d4*4+2] = v.z; wks[j*65 + d4*4+3] = v.w;
    }
    for (int i = t; i < 16*64; i += 256) {
        int bb = i >> 6, d = i & 63;
        qhs[bb*64 + d] = g_q[bb*NE + h*ND + d];
    }
    __syncthreads();

    const int j = t & 63, bg = t >> 6;
    float acc[4] = {0.f,0.f,0.f,0.f};
    const float* wr = wks + j*65;
    #pragma unroll
    for (int d = 0; d < 64; ++d) {
        float wv = wr[d];
        #pragma unroll
        for (int bb = 0; bb < 4; ++bb)
            acc[bb] = fmaf(wv, qhs[(bg*4 + bb)*64 + d], acc[bb]);
    }
    #pragma unroll
    for (int bb = 0; bb < 4; ++bb)
        g_P[((size_t)(bg*4 + bb)*NH + h)*NKV + jb*64 + j] = acc[bb]*0.125f;
}

// ---------------------------------------------------------------------------
// B: fused pass over kv, both inner products on tensor cores (tf32 mma).
// TILE=16 rows, ~106 KB smem -> 2 CTAs/SM (co-resident CTA hides barrier
// skew + mma dependency chains). 256 threads / 8 warps. Per tile:
//  1) logit GEMM: warp ks=wid -> partial C[16 rows][8 heads] over its
//     64-wide K slice (8 mmas); partials -> smem.
//  2) 128 threads reduce 8 K slices, one exp; w tf32-rounded, SAME value
//     feeds Z and the stored weight.
//  3) accumulation GEMM: ctx^T += kv^T @ w; warp owns 64 cols (4 m16-tiles)
//     x 8 heads x K=16 (2 k8-chunks) = 8 mmas; acc (16 regs) persists;
//     each (col,head) owned by ONE warp -> direct STG epilogue.
// No-max softmax (|logit| < ~3). Triple-buffered cp.async (distance 2);
// ROWF=516 keeps logit A-frags conflict-free (accum A-frags 2-way).
// ---------------------------------------------------------------------------
__global__ void __launch_bounds__(TB, 2) kernB(const float* __restrict__ kv)
{
    extern __shared__ float sh[];
    float* kvs  = sh;                          // [3][TILE][ROWF]
    float* wsm  = sh + 3*TILE*ROWF;            // [2][TILE][NH] tf32 weights
    float* part = wsm + 2*TILE*NH;             // [8 warps][16 rows][8 heads]
    float* zs   = part + 8*16*8;               // [128]

    const int tid  = threadIdx.x;
    const int wid  = tid >> 5, lane = tid & 31;
    const int chunk = blockIdx.x, b = blockIdx.y;

    // shared lane decomposition for mma fragments
    const int gr = lane >> 2, gc = lane & 3;
    // logit-phase mapping: warp = K slice of 64
    const int ks = wid;
    // reduction mapping (tid < 128)
    const int rrow = tid >> 3, rh = tid & 7;
    // accum-phase mapping: warp owns cols wid*64..+63

    // Logit B fragments: P^T slice (64-wide), tf32, in registers.
    unsigned bq0[8], bq1[8];
    {
        const float* Ph = g_P + ((size_t)b*NH + gr)*NKV + ks*64 + gc;
        #pragma unroll
        for (int kb = 0; kb < 8; ++kb) {
            bq0[kb] = to_tf32(Ph[kb*8]);
            bq1[kb] = to_tf32(Ph[kb*8 + 4]);
        }
    }

    // Accum accumulators: D^T[col0+mt*16+{gr,gr+8}][{2gc,2gc+1}]
    float acc[4][4];
    #pragma unroll
    for (int mt = 0; mt < 4; ++mt)
        #pragma unroll
        for (int c = 0; c < 4; ++c) acc[mt][c] = 0.f;
    float zacc = 0.f;

    const unsigned kvs_u = (unsigned)__cvta_generic_to_shared(kvs);
    const float4* src_base = (const float4*)kv
        + ((size_t)b*NS + (size_t)chunk*CHUNK)*(NKV/4);

    // prologue: stage tiles 0 and 1 (padded rows: dst float4 index r*129+c4)
    #pragma unroll
    for (int pt = 0; pt < 2; ++pt) {
        const float4* s = src_base + (size_t)pt*TILE*(NKV/4);
        unsigned dst = kvs_u + (unsigned)(pt*TILE*ROWF*4);
        #pragma unroll
        for (int k = 0; k < (TILE*NKV/4)/TB; ++k) {
            int i = tid + k*TB;
            int r = i >> 7, c4 = i & 127;
            cpa16(dst + (unsigned)((r*129 + c4)*16), s + i);
        }
        asm volatile("cp.async.commit_group;");
    }

    for (int t = 0; t < NTILES; ++t) {
        if (t < NTILES-1) asm volatile("cp.async.wait_group 1;");
        else              asm volatile("cp.async.wait_group 0;");
        __syncthreads();                                   // B1

        if (t + 2 < NTILES) {   // stage t+2 into buffer (t+2)%3
            const float4* s = src_base + (size_t)(t+2)*TILE*(NKV/4);
            unsigned dst = kvs_u + (unsigned)(((t+2)%3)*TILE*ROWF*4);
            #pragma unroll
            for (int k = 0; k < (TILE*NKV/4)/TB; ++k) {
                int i = tid + k*TB;
                int r = i >> 7, c4 = i & 127;
                cpa16(dst + (unsigned)((r*129 + c4)*16), s + i);
            }
            asm volatile("cp.async.commit_group;");
        }

        const float* buf = kvs + (t%3)*TILE*ROWF;

        // ---- 1) logit mma: partial C over this warp's 64-wide K slice ----
        {
            const float* pa = buf + gr*ROWF + ks*64 + gc;
            float c0=0.f, c1=0.f, c2=0.f, c3=0.f;
            float d0=0.f, d1=0.f, d2=0.f, d3=0.f;   // split chain 2-way
            #pragma unroll
            for (int kb = 0; kb < 8; kb += 2) {
                const float* p = pa + kb*8;
                mma_tf32(c0, c1, c2, c3,
                         __float_as_uint(p[0]), __float_as_uint(p[8*ROWF]),
                         __float_as_uint(p[4]), __float_as_uint(p[8*ROWF + 4]),
                         bq0[kb], bq1[kb]);
                const float* p2 = pa + (kb+1)*8;
                mma_tf32(d0, d1, d2, d3,
                         __float_as_uint(p2[0]), __float_as_uint(p2[8*ROWF]),
                         __float_as_uint(p2[4]), __float_as_uint(p2[8*ROWF + 4]),
                         bq0[kb+1], bq1[kb+1]);
            }
            *(float2*)(part + wid*128 + gr*8 + 2*gc)     = make_float2(c0+d0, c1+d1);
            *(float2*)(part + wid*128 + (gr+8)*8 + 2*gc) = make_float2(c2+d2, c3+d3);
        }
        __syncthreads();                                   // B2

        // ---- 2) reduce 8 K slices, exp, tf32-round, store ----
        if (tid < 128) {
            const int off = rrow*8 + rh;
            float p0 = part[0*128 + off], p1 = part[1*128 + off];
            float p2 = part[2*128 + off], p3 = part[3*128 + off];
            float p4 = part[4*128 + off], p5 = part[5*128 + off];
            float p6 = part[6*128 + off], p7 = part[7*128 + off];
            float lg = ((p0+p1)+(p2+p3)) + ((p4+p5)+(p6+p7));
            float w = __expf(lg);
            float wf = __uint_as_float(to_tf32(w));   // tf32-rounded weight
            zacc += wf;                               // Z from the SAME value
            wsm[(t & 1)*TILE*NH + rrow*NH + rh] = wf;
        }
        __syncthreads();                                   // B3

        // ---- 3) accumulation mma: ctx^T += kv^T @ w ----
        {
            const float* wt = wsm + (t & 1)*TILE*NH;
            const int col0 = wid*64;
            #pragma unroll
            for (int kc = 0; kc < 2; ++kc) {
                unsigned b0 = __float_as_uint(wt[(kc*8 + gc)*NH + gr]);
                unsigned b1 = __float_as_uint(wt[(kc*8 + gc + 4)*NH + gr]);
                const float* ar0 = buf + (kc*8 + gc)*ROWF + col0 + gr;
                const float* ar1 = buf + (kc*8 + gc + 4)*ROWF + col0 + gr;
                #pragma unroll
                for (int mt = 0; mt < 4; ++mt) {
                    unsigned a0 = __float_as_uint(ar0[mt*16]);
                    unsigned a1 = __float_as_uint(ar0[mt*16 + 8]);
                    unsigned a2 = __float_as_uint(ar1[mt*16]);
                    unsigned a3 = __float_as_uint(ar1[mt*16 + 8]);
                    mma_tf32(acc[mt][0], acc[mt][1], acc[mt][2], acc[mt][3],
                             a0, a1, a2, a3, b0, b1);
                }
            }
        }
    }

    // ---- epilogue: direct STG (each warp owns its cols x all heads) ----
    if (tid < 128) zs[tid] = zacc;
    __syncthreads();

    const int part_i = b*NCHUNK + chunk;
    {
        float* pc = g_partC + (size_t)part_i*NH*NKV;
        const int col0 = wid*64 + gr;
        #pragma unroll
        for (int mt = 0; mt < 4; ++mt) {
            const int col = col0 + mt*16;
            pc[(size_t)(2*gc  )*NKV + col    ] = acc[mt][0];
            pc[(size_t)(2*gc+1)*NKV + col    ] = acc[mt][1];
            pc[(size_t)(2*gc  )*NKV + col + 8] = acc[mt][2];
            pc[(size_t)(2*gc+1)*NKV + col + 8] = acc[mt][3];
        }
    }
    if (tid < NH) {
        float Z = 0.f;
        #pragma unroll
        for (int j = 0; j < 16; ++j) Z += zs[j*8 + tid];
        g_partZ[part_i*NH + tid] = Z;
    }
}

// ---------------------------------------------------------------------------
// C1: cbar[b,h,j] = (sum_i partC[b,i,h,j]) / Z[b,h].  grid 64 x 256
// ---------------------------------------------------------------------------
__global__ void __launch_bounds__(256) kernC1()
{
    const int idx = blockIdx.x*256 + threadIdx.x;      // 16384 float4 slots
    const int b = idx >> 10, rem = idx & 1023, h = rem >> 7, j4 = rem & 127;
    float Z = 0.f;
    #pragma unroll
    for (int i = 0; i < NCHUNK; ++i) Z += g_partZ[(b*NCHUNK + i)*NH + h];
    const float invZ = 1.0f / Z;
    float4 s = make_float4(0.f,0.f,0.f,0.f);
    #pragma unroll
    for (int i = 0; i < NCHUNK; ++i) {
        const float4* p = (const float4*)(g_partC + (((size_t)(b*NCHUNK + i)*NH + h) << 9));
        float4 v = p[j4];
        s.x += v.x; s.y += v.y; s.z += v.z; s.w += v.w;
    }
    s.x *= invZ; s.y *= invZ; s.z *= invZ; s.w *= invZ;
    ((float4*)g_cbar)[((size_t)(b*NH + h) << 7) + j4] = s;
}

// ---------------------------------------------------------------------------
// C2: ctx[b, h*64+col] = cbar[b,h,:] @ Wv[:, h*64+col] + bv.
// ---------------------------------------------------------------------------
__global__ void __launch_bounds__(256) kernC2(
    const float* __restrict__ Wv, const float* __restrict__ bv)
{
    __shared__ float cb_s[NKV];
    __shared__ float red[256];
    const int b = blockIdx.x, h = blockIdx.y, t = threadIdx.x;
    for (int i = t; i < NKV; i += 256) cb_s[i] = g_cbar[(size_t)(b*NH + h)*NKV + i];
    __syncthreads();
    const int col = h*64 + (t & 63), kp = t >> 6;
    const float* c  = cb_s + kp*128;
    const float* wv = Wv + (size_t)(kp*128)*NE + col;
    float s0=0,s1=0,s2=0,s3=0,s4=0,s5=0,s6=0,s7=0;
    #pragma unroll 4
    for (int j = 0; j < 128; j += 8) {
        s0 = fmaf(c[j+0], wv[(size_t)(j+0)*NE], s0);
        s1 = fmaf(c[j+1], wv[(size_t)(j+1)*NE], s1);
        s2 = fmaf(c[j+2], wv[(size_t)(j+2)*NE], s2);
        s3 = fmaf(c[j+3], wv[(size_t)(j+3)*NE], s3);
        s4 = fmaf(c[j+4], wv[(size_t)(j+4)*NE], s4);
        s5 = fmaf(c[j+5], wv[(size_t)(j+5)*NE], s5);
        s6 = fmaf(c[j+6], wv[(size_t)(j+6)*NE], s6);
        s7 = fmaf(c[j+7], wv[(size_t)(j+7)*NE], s7);
    }
    red[t] = ((s0+s1)+(s2+s3))+((s4+s5)+(s6+s7));
    __syncthreads();
    if (t < 64)
        g_ctx[b*NE + col] = ((red[t]+red[t+64])+(red[t+128]+red[t+192])) + bv[col];
}

// ---------------------------------------------------------------------------
// D: out[b] = ctx[b] @ Wo + bo.
// ---------------------------------------------------------------------------
__global__ void __launch_bounds__(256) kernD(
    const float* __restrict__ Wo, const float* __restrict__ bo,
    float* __restrict__ out)
{
    __shared__ float cs[NE];
    __shared__ float red[256];
    const int b = blockIdx.x, cb = blockIdx.y, t = threadIdx.x;
    for (int i = t; i < NE; i += 256) cs[i] = g_ctx[b*NE + i];
    __syncthreads();
    const int col = cb*64 + (t & 63), kp = t >> 6;
    const float* c  = cs + kp*128;
    const float* wo = Wo + (size_t)(kp*128)*NE + col;
    float s0=0,s1=0,s2=0,s3=0,s4=0,s5=0,s6=0,s7=0;
    #pragma unroll 4
    for (int j = 0; j < 128; j += 8) {
        s0 = fmaf(c[j+0], wo[(size_t)(j+0)*NE], s0);
        s1 = fmaf(c[j+1], wo[(size_t)(j+1)*NE], s1);
        s2 = fmaf(c[j+2], wo[(size_t)(j+2)*NE], s2);
        s3 = fmaf(c[j+3], wo[(size_t)(j+3)*NE], s3);
        s4 = fmaf(c[j+4], wo[(size_t)(j+4)*NE], s4);
        s5 = fmaf(c[j+5], wo[(size_t)(j+5)*NE], s5);
        s6 = fmaf(c[j+6], wo[(size_t)(j+6)*NE], s6);
        s7 = fmaf(c[j+7], wo[(size_t)(j+7)*NE], s7);
    }
    red[t] = ((s0+s1)+(s2+s3))+((s4+s5)+(s6+s7));
    __syncthreads();
    if (t < 64)
        out[b*NE + col] = ((red[t]+red[t+64])+(red[t+128]+red[t+192])) + bo[col];
}

// ---------------------------------------------------------------------------
extern "C" void kernel_launch(void* const* d_in, const int* in_sizes, int n_in,
                              void* d_out, int out_size)
{
    (void)in_sizes; (void)n_in; (void)out_size;
    const float* query = (const float*)d_in[0];
    const float* kv    = (const float*)d_in[1];
    const float* Wq    = (const float*)d_in[2];
    const float* bq    = (const float*)d_in[3];
    const float* Wk    = (const float*)d_in[4];
    // d_in[5] = bk: softmax-invariant, unused
    const float* Wv    = (const float*)d_in[6];
    const float* bv    = (const float*)d_in[7];
    const float* Wo    = (const float*)d_in[8];
    const float* bo    = (const float*)d_in[9];
    float* out = (float*)d_out;

    const size_t shmB = (size_t)(3*TILE*ROWF + 2*TILE*NH + 8*16*8 + 128)
                        * sizeof(float);
    cudaFuncSetAttribute(kernB, cudaFuncAttributeMaxDynamicSharedMemorySize, (int)shmB);

    kernA1<<<dim3(NB, 8), 256>>>(query, Wq, bq);
    kernA2<<<dim3(8, NH), 256>>>(Wk);
    kernB <<<dim3(NCHUNK, NB), TB, shmB>>>(kv);
    kernC1<<<64, 256>>>();
    kernC2<<<dim3(NB, NH), 256>>>(Wv, bv);
    kernD <<<dim3(NB, 8), 256>>>(Wo, bo, out);
}